// round 2
// baseline (speedup 1.0000x reference)
#include <cuda_runtime.h>
#include <mma.h>
#include <cstdint>

using namespace nvcuda;

// Problem constants (shapes fixed by the dataset)
#define NN      100000          // nodes
#define PADN    100096          // 782 * 128 : padded rows for guard-free GEMM stores
#define NE      1600000         // edges per list
#define IN_DIM  512
#define OUT_DIM 128

// ---------------------------------------------------------------------------
// Scratch (no cudaMalloc allowed -> __device__ globals)
// ---------------------------------------------------------------------------
__device__ float g_xw[(size_t)4 * PADN * OUT_DIM];   // xw1,xw2,xw3,xw4 (padded rows)
__device__ float g_h [(size_t)4 * NN   * OUT_DIM];   // h1,h2,h3,h4
__device__ int   g_deg[2 * NN];
__device__ int   g_S  [2 * NN];                      // inclusive scan of deg
__device__ int   g_cur[2 * NN];                      // scatter cursors
__device__ int   g_csr[2 * NE];                      // src ids grouped by dst
__device__ int   g_bsums[512];
__device__ float g_colsum[256];                      // colsum(h1), colsum(h2)
__device__ float g_v[256];                           // v1 = Wb@c1, v2 = Wb@c2

// ---------------------------------------------------------------------------
// Zero helpers
// ---------------------------------------------------------------------------
__global__ void zero_int(int* p, int n) {
    int g = blockIdx.x * blockDim.x + threadIdx.x;
    if (g < n) p[g] = 0;
}
__global__ void zero_float(float* p, int n) {
    int g = blockIdx.x * blockDim.x + threadIdx.x;
    if (g < n) p[g] = 0.0f;
}

// ---------------------------------------------------------------------------
// GEMM: out[M,128] = X[M,512] @ W[512,128], tf32 wmma, 128x128 block tile
// out is padded to PADN rows so stores need no guard.
// ---------------------------------------------------------------------------
__global__ __launch_bounds__(256) void gemm_tf32(
    const float* __restrict__ X, const float* __restrict__ W,
    float* __restrict__ out, int n_rows)
{
    __shared__ float As[128][40];   // 128 rows x 32 k  (pad 40: 160B rows, 32B aligned frags)
    __shared__ float Bs[32][136];   // 32 k x 128 n     (pad 136)

    const int tid  = threadIdx.x;
    const int warp = tid >> 5;
    const int m0   = blockIdx.x * 128;
    const int wm   = (warp & 3) * 32;   // warp row offset
    const int wn   = (warp >> 2) * 64;  // warp col offset

    wmma::fragment<wmma::accumulator, 16, 16, 8, float> acc[2][4];
    #pragma unroll
    for (int i = 0; i < 2; i++)
        #pragma unroll
        for (int j = 0; j < 4; j++) wmma::fill_fragment(acc[i][j], 0.0f);

    for (int k0 = 0; k0 < IN_DIM; k0 += 32) {
        // Load A tile: 128x32 floats = 1024 float4
        #pragma unroll
        for (int i = 0; i < 4; i++) {
            int p = tid + i * 256;
            int r = p >> 3;
            int c = (p & 7) << 2;
            float4 v = make_float4(0.f, 0.f, 0.f, 0.f);
            int gr = m0 + r;
            if (gr < n_rows) v = *(const float4*)(X + (size_t)gr * IN_DIM + k0 + c);
            v.x = wmma::__float_to_tf32(v.x);
            v.y = wmma::__float_to_tf32(v.y);
            v.z = wmma::__float_to_tf32(v.z);
            v.w = wmma::__float_to_tf32(v.w);
            *(float4*)&As[r][c] = v;
        }
        // Load B tile: 32x128 floats = 1024 float4
        #pragma unroll
        for (int i = 0; i < 4; i++) {
            int p = tid + i * 256;
            int r = p >> 5;
            int c = (p & 31) << 2;
            float4 v = *(const float4*)(W + (size_t)(k0 + r) * OUT_DIM + c);
            v.x = wmma::__float_to_tf32(v.x);
            v.y = wmma::__float_to_tf32(v.y);
            v.z = wmma::__float_to_tf32(v.z);
            v.w = wmma::__float_to_tf32(v.w);
            *(float4*)&Bs[r][c] = v;
        }
        __syncthreads();

        #pragma unroll
        for (int kk = 0; kk < 4; kk++) {
            wmma::fragment<wmma::matrix_a, 16, 16, 8, wmma::precision::tf32, wmma::row_major> a[2];
            wmma::fragment<wmma::matrix_b, 16, 16, 8, wmma::precision::tf32, wmma::row_major> b[4];
            wmma::load_matrix_sync(a[0], &As[wm][kk * 8], 40);
            wmma::load_matrix_sync(a[1], &As[wm + 16][kk * 8], 40);
            #pragma unroll
            for (int j = 0; j < 4; j++)
                wmma::load_matrix_sync(b[j], &Bs[kk * 8][wn + j * 16], 136);
            #pragma unroll
            for (int i = 0; i < 2; i++)
                #pragma unroll
                for (int j = 0; j < 4; j++)
                    wmma::mma_sync(acc[i][j], a[i], b[j], acc[i][j]);
        }
        __syncthreads();
    }

    #pragma unroll
    for (int i = 0; i < 2; i++)
        #pragma unroll
        for (int j = 0; j < 4; j++)
            wmma::store_matrix_sync(out + (size_t)(m0 + wm + i * 16) * OUT_DIM + wn + j * 16,
                                    acc[i][j], OUT_DIM, wmma::mem_row_major);
}

// ---------------------------------------------------------------------------
// CSR build: histogram -> block scan -> scatter
// ---------------------------------------------------------------------------
__global__ void hist_kernel(const int* __restrict__ dst, int* __restrict__ deg, int n) {
    int g = blockIdx.x * blockDim.x + threadIdx.x;
    if (g < n) atomicAdd(&deg[dst[g]], 1);
}

__global__ void scan_partial(const int* __restrict__ in, int* __restrict__ out,
                             int* __restrict__ bsums, int n)
{
    __shared__ int tmp[512];
    int tid = threadIdx.x;
    int g = blockIdx.x * 512 + tid;
    int v = (g < n) ? in[g] : 0;
    tmp[tid] = v;
    __syncthreads();
    #pragma unroll
    for (int off = 1; off < 512; off <<= 1) {
        int t = (tid >= off) ? tmp[tid - off] : 0;
        __syncthreads();
        tmp[tid] += t;
        __syncthreads();
    }
    if (g < n) out[g] = tmp[tid];
    if (tid == 511) bsums[blockIdx.x] = tmp[511];
}

__global__ void scan_bsums(int* bsums, int nb) {   // -> exclusive scan, one block
    __shared__ int tmp[256];
    int tid = threadIdx.x;
    int v = (tid < nb) ? bsums[tid] : 0;
    tmp[tid] = v;
    __syncthreads();
    #pragma unroll
    for (int off = 1; off < 256; off <<= 1) {
        int t = (tid >= off) ? tmp[tid - off] : 0;
        __syncthreads();
        tmp[tid] += t;
        __syncthreads();
    }
    if (tid < nb) bsums[tid] = tmp[tid] - v;   // exclusive
}

__global__ void scan_add(int* __restrict__ S, const int* __restrict__ bsums,
                         const int* __restrict__ deg, int* __restrict__ cur, int n)
{
    int g = blockIdx.x * blockDim.x + threadIdx.x;
    if (g < n) {
        int s = S[g] + bsums[g >> 9];
        S[g] = s;               // inclusive scan
        cur[g] = s - deg[g];    // row start (scatter cursor)
    }
}

__global__ void scatter_kernel(const int* __restrict__ src, const int* __restrict__ dst,
                               int* __restrict__ cur, int* __restrict__ csr, int n)
{
    int g = blockIdx.x * blockDim.x + threadIdx.x;
    if (g < n) {
        int pos = atomicAdd(&cur[dst[g]], 1);
        csr[pos] = src[g];
    }
}

// ---------------------------------------------------------------------------
// Aggregation: h[dst] = sum(xw[src]) + b, warp per node, float4 per lane.
// Optionally accumulates column sums (for the sigmoid-mean readout).
// ---------------------------------------------------------------------------
template <int COLSUM>
__global__ __launch_bounds__(256) void agg_kernel(
    const float* __restrict__ xw, const int* __restrict__ S, const int* __restrict__ csr,
    const float* __restrict__ b, float* __restrict__ h, float* __restrict__ colsum, int n)
{
    __shared__ float sred[8][128];
    int warp = threadIdx.x >> 5, lane = threadIdx.x & 31;
    int node = blockIdx.x * 8 + warp;
    bool valid = node < n;

    float4 acc = make_float4(0.f, 0.f, 0.f, 0.f);
    if (valid) {
        int start = (node == 0) ? 0 : S[node - 1];
        int end = S[node];
        const float4* xw4 = (const float4*)xw;
        for (int e = start; e < end; e++) {
            int s = csr[e];
            float4 v = xw4[(size_t)s * 32 + lane];
            acc.x += v.x; acc.y += v.y; acc.z += v.z; acc.w += v.w;
        }
        float4 bv = ((const float4*)b)[lane];
        acc.x += bv.x; acc.y += bv.y; acc.z += bv.z; acc.w += bv.w;
        ((float4*)h)[(size_t)node * 32 + lane] = acc;
    }

    if (COLSUM) {
        if (!valid) acc = make_float4(0.f, 0.f, 0.f, 0.f);
        *(float4*)&sred[warp][lane * 4] = acc;
        __syncthreads();
        int t = threadIdx.x;
        if (t < 128) {
            float s = 0.f;
            #pragma unroll
            for (int w = 0; w < 8; w++) s += sred[w][t];
            atomicAdd(&colsum[t], s);
        }
    }
}

// ---------------------------------------------------------------------------
// c = sigmoid(colsum / n) ; v = Wb @ c (v[d] = sum_e Wb[d,e] c[e])
// ---------------------------------------------------------------------------
__global__ void cv_kernel(const float* __restrict__ Wb,
                          const float* __restrict__ cs1, const float* __restrict__ cs2,
                          float* __restrict__ v1, float* __restrict__ v2, float inv_n)
{
    __shared__ float c1s[128], c2s[128];
    int t = threadIdx.x;  // 128 threads
    c1s[t] = 1.0f / (1.0f + expf(-cs1[t] * inv_n));
    c2s[t] = 1.0f / (1.0f + expf(-cs2[t] * inv_n));
    __syncthreads();
    float a = 0.f, b = 0.f;
    #pragma unroll 8
    for (int e = 0; e < 128; e++) {
        float w = Wb[t * 128 + e];
        a += w * c1s[e];
        b += w * c2s[e];
    }
    v1[t] = a;
    v2[t] = b;
}

// ---------------------------------------------------------------------------
// Score: out[n] = dot(h[n,:], v) + bb  (warp per node)
// ---------------------------------------------------------------------------
__global__ __launch_bounds__(256) void score_kernel(
    const float* __restrict__ h, const float* __restrict__ v,
    const float* __restrict__ bbp, float* __restrict__ out, int n)
{
    int warp = threadIdx.x >> 5, lane = threadIdx.x & 31;
    int node = blockIdx.x * 8 + warp;
    if (node >= n) return;
    float4 hv = ((const float4*)h)[(size_t)node * 32 + lane];
    float4 vv = ((const float4*)v)[lane];
    float s = hv.x * vv.x + hv.y * vv.y + hv.z * vv.z + hv.w * vv.w;
    s += __shfl_xor_sync(0xffffffffu, s, 16);
    s += __shfl_xor_sync(0xffffffffu, s, 8);
    s += __shfl_xor_sync(0xffffffffu, s, 4);
    s += __shfl_xor_sync(0xffffffffu, s, 2);
    s += __shfl_xor_sync(0xffffffffu, s, 1);
    if (lane == 0) out[node] = s + bbp[0];
}

// ---------------------------------------------------------------------------
// Launch
// ---------------------------------------------------------------------------
extern "C" void kernel_launch(void* const* d_in, const int* in_sizes, int n_in,
                              void* d_out, int out_size)
{
    const float* feat = (const float*)d_in[0];
    const float* shuf = (const float*)d_in[1];
    const int*   src1 = (const int*)d_in[2];
    const int*   dst1 = (const int*)d_in[3];
    const int*   src2 = (const int*)d_in[4];
    const int*   dst2 = (const int*)d_in[5];
    const float* W1   = (const float*)d_in[6];
    const float* b1   = (const float*)d_in[7];
    const float* W2   = (const float*)d_in[8];
    const float* b2   = (const float*)d_in[9];
    const float* Wb   = (const float*)d_in[10];
    const float* bb   = (const float*)d_in[11];
    float* out = (float*)d_out;

    const int n   = in_sizes[0] / IN_DIM;   // 100000
    const int ne1 = in_sizes[2];
    const int ne2 = in_sizes[4];

    void* p;
    cudaGetSymbolAddress(&p, g_xw);     float* xw  = (float*)p;
    cudaGetSymbolAddress(&p, g_h);      float* h   = (float*)p;
    cudaGetSymbolAddress(&p, g_deg);    int*   deg = (int*)p;
    cudaGetSymbolAddress(&p, g_S);      int*   S   = (int*)p;
    cudaGetSymbolAddress(&p, g_cur);    int*   cur = (int*)p;
    cudaGetSymbolAddress(&p, g_csr);    int*   csr = (int*)p;
    cudaGetSymbolAddress(&p, g_bsums);  int*   bs  = (int*)p;
    cudaGetSymbolAddress(&p, g_colsum); float* cs  = (float*)p;
    cudaGetSymbolAddress(&p, g_v);      float* v   = (float*)p;

    const size_t XWS = (size_t)PADN * OUT_DIM;
    const size_t HS  = (size_t)NN * OUT_DIM;
    float* xw1 = xw;            // feat @ W1
    float* xw2 = xw + XWS;      // feat @ W2
    float* xw3 = xw + 2 * XWS;  // shuf @ W1
    float* xw4 = xw + 3 * XWS;  // shuf @ W2
    float* h1 = h;
    float* h2 = h + HS;
    float* h3 = h + 2 * HS;
    float* h4 = h + 3 * HS;

    // 0) zero degree + colsum scratch
    zero_int<<<(2 * NN + 255) / 256, 256>>>(deg, 2 * NN);
    zero_float<<<1, 256>>>(cs, 256);

    // 1) GEMMs (tf32)
    int mg = (n + 127) / 128;   // 782
    gemm_tf32<<<mg, 256>>>(feat, W1, xw1, n);
    gemm_tf32<<<mg, 256>>>(feat, W2, xw2, n);
    gemm_tf32<<<mg, 256>>>(shuf, W1, xw3, n);
    gemm_tf32<<<mg, 256>>>(shuf, W2, xw4, n);

    // 2) CSR build for both edge lists
    hist_kernel<<<(ne1 + 255) / 256, 256>>>(dst1, deg, ne1);
    hist_kernel<<<(ne2 + 255) / 256, 256>>>(dst2, deg + NN, ne2);
    int nbs = (n + 511) / 512;  // 196
    scan_partial<<<nbs, 512>>>(deg, S, bs, n);
    scan_partial<<<nbs, 512>>>(deg + NN, S + NN, bs + 256, n);
    scan_bsums<<<1, 256>>>(bs, nbs);
    scan_bsums<<<1, 256>>>(bs + 256, nbs);
    scan_add<<<(n + 255) / 256, 256>>>(S, bs, deg, cur, n);
    scan_add<<<(n + 255) / 256, 256>>>(S + NN, bs + 256, deg + NN, cur + NN, n);
    scatter_kernel<<<(ne1 + 255) / 256, 256>>>(src1, dst1, cur, csr, ne1);
    scatter_kernel<<<(ne2 + 255) / 256, 256>>>(src2, dst2, cur + NN, csr + NE, ne2);

    // 3) Aggregations (colsum fused for h1, h2)
    int nb = (n + 7) / 8;  // 12500
    agg_kernel<1><<<nb, 256>>>(xw1, S, csr, b1, h1, cs, n);
    agg_kernel<1><<<nb, 256>>>(xw2, S + NN, csr + NE, b2, h2, cs + 128, n);
    agg_kernel<0><<<nb, 256>>>(xw3, S, csr, b1, h3, nullptr, n);
    agg_kernel<0><<<nb, 256>>>(xw4, S + NN, csr + NE, b2, h4, nullptr, n);

    // 4) readout vectors
    cv_kernel<<<1, 128>>>(Wb, cs, cs + 128, v, v + 128, 1.0f / (float)n);

    // 5) scores: [h2.v1, h1.v2, h4.v1, h3.v2]
    score_kernel<<<nb, 256>>>(h2, v,       bb, out,         n);
    score_kernel<<<nb, 256>>>(h1, v + 128, bb, out + n,     n);
    score_kernel<<<nb, 256>>>(h4, v,       bb, out + 2 * n, n);
    score_kernel<<<nb, 256>>>(h3, v + 128, bb, out + 3 * n, n);
}

// round 3
// speedup vs baseline: 3.3797x; 3.3797x over previous
#include <cuda_runtime.h>
#include <cstdint>
#include <math.h>

#define NN      100000
#define IN_DIM  512
#define OUT_DIM 128

// ---------------------------------------------------------------------------
// Scratch (__device__ globals; no cudaMalloc allowed). ~2.5 MB total.
// ---------------------------------------------------------------------------
__device__ int   g_deg[2 * NN];          // outdeg over src1, src2
__device__ float g_wf [2 * IN_DIM];      // weighted row-sums of feat
__device__ float g_u  [2 * IN_DIM];      // u_a = W2@v1, u_b = W1@v2
__device__ float g_k  [2];               // k1 = b2.v1+bb, k2 = b1.v2+bb
__device__ float g_p  [4 * NN];          // pfa, pfb, psa, psb

// ---------------------------------------------------------------------------
// Histogram: outdeg[src[e]]++  (4 edges per thread)
// ---------------------------------------------------------------------------
__global__ void hist4(const int* __restrict__ src, int* __restrict__ deg, int ne)
{
    int base = blockIdx.x * 1024 + threadIdx.x;
    #pragma unroll
    for (int j = 0; j < 4; j++) {
        int e = base + j * 256;
        if (e < ne) atomicAdd(&deg[src[e]], 1);
    }
}

// ---------------------------------------------------------------------------
// wf[c]      = sum_v outdeg1[v] * feat[v,c]
// wf[512+c]  = sum_v outdeg2[v] * feat[v,c]
// 256 threads: thread t owns columns t and t+256. Block-strided rows, local
// accumulation, 4 atomics per thread at the end.
// ---------------------------------------------------------------------------
__global__ __launch_bounds__(256) void wf_kernel(
    const float* __restrict__ feat, const int* __restrict__ deg1,
    const int* __restrict__ deg2, float* __restrict__ wf, int n)
{
    int t = threadIdx.x;
    float a0 = 0.f, a1 = 0.f, b0 = 0.f, b1 = 0.f;
    for (int v = blockIdx.x; v < n; v += gridDim.x) {
        float w1 = (float)__ldg(&deg1[v]);
        float w2 = (float)__ldg(&deg2[v]);
        const float* row = feat + (size_t)v * IN_DIM;
        float x0 = __ldg(&row[t]);
        float x1 = __ldg(&row[t + 256]);
        a0 += w1 * x0; a1 += w1 * x1;
        b0 += w2 * x0; b1 += w2 * x1;
    }
    atomicAdd(&wf[t],             a0);
    atomicAdd(&wf[t + 256],       a1);
    atomicAdd(&wf[IN_DIM + t],       b0);
    atomicAdd(&wf[IN_DIM + t + 256], b1);
}

// ---------------------------------------------------------------------------
// Tiny serial chain (all small vectors), one block of 512 threads:
//   c1 = sigmoid(wf1@W1 / n + b1)    c2 = sigmoid(wf2@W2 / n + b2)
//   v1 = Wb@c1                       v2 = Wb@c2
//   u_a = W2@v1                      u_b = W1@v2
//   k1 = b2.v1 + bb                  k2 = b1.v2 + bb
// ---------------------------------------------------------------------------
__global__ __launch_bounds__(512) void tiny_kernel(
    const float* __restrict__ W1, const float* __restrict__ b1,
    const float* __restrict__ W2, const float* __restrict__ b2,
    const float* __restrict__ Wb, const float* __restrict__ bb,
    const float* __restrict__ wf, float* __restrict__ u,
    float* __restrict__ kc, float inv_n)
{
    __shared__ float c1[128], c2[128], v1[128], v2[128];
    int t = threadIdx.x;

    // phase A: c vectors
    if (t < 128) {
        float s = 0.f;
        #pragma unroll 8
        for (int k = 0; k < IN_DIM; k++) s += wf[k] * W1[k * OUT_DIM + t];
        c1[t] = 1.0f / (1.0f + expf(-(s * inv_n + b1[t])));
    } else if (t < 256) {
        int tt = t - 128;
        float s = 0.f;
        #pragma unroll 8
        for (int k = 0; k < IN_DIM; k++) s += wf[IN_DIM + k] * W2[k * OUT_DIM + tt];
        c2[tt] = 1.0f / (1.0f + expf(-(s * inv_n + b2[tt])));
    }
    __syncthreads();

    // phase B: v vectors
    if (t < 128) {
        float s = 0.f;
        #pragma unroll 8
        for (int e = 0; e < 128; e++) s += Wb[t * 128 + e] * c1[e];
        v1[t] = s;
    } else if (t < 256) {
        int tt = t - 128;
        float s = 0.f;
        #pragma unroll 8
        for (int e = 0; e < 128; e++) s += Wb[tt * 128 + e] * c2[e];
        v2[tt] = s;
    }
    __syncthreads();

    // phase C: u vectors (512 threads, one row each)
    {
        float sa = 0.f, sb = 0.f;
        #pragma unroll 8
        for (int d = 0; d < 128; d++) {
            sa += W2[t * OUT_DIM + d] * v1[d];
            sb += W1[t * OUT_DIM + d] * v2[d];
        }
        u[t] = sa;
        u[IN_DIM + t] = sb;
    }

    // phase D: constants
    if (t == 0) {
        float s1 = 0.f, s2 = 0.f;
        for (int d = 0; d < 128; d++) { s1 += b2[d] * v1[d]; s2 += b1[d] * v2[d]; }
        float b = bb[0];
        kc[0] = s1 + b;
        kc[1] = s2 + b;
    }
}

// ---------------------------------------------------------------------------
// p GEMVs: pa[v] = X[v,:].u_a ; pb[v] = X[v,:].u_b   (warp per node)
// ---------------------------------------------------------------------------
__global__ __launch_bounds__(256) void p_kernel(
    const float* __restrict__ X, const float* __restrict__ u,
    float* __restrict__ pa, float* __restrict__ pb, int n)
{
    __shared__ __align__(16) float su[2 * IN_DIM];
    for (int i = threadIdx.x; i < 2 * IN_DIM; i += 256) su[i] = u[i];
    __syncthreads();

    int warp = threadIdx.x >> 5, lane = threadIdx.x & 31;
    const float4* ua4 = (const float4*)su;
    const float4* ub4 = (const float4*)(su + IN_DIM);

    for (int v = blockIdx.x * 8 + warp; v < n; v += gridDim.x * 8) {
        const float4* x4 = (const float4*)(X + (size_t)v * IN_DIM);
        float sa = 0.f, sb = 0.f;
        #pragma unroll
        for (int j = 0; j < 4; j++) {
            float4 x = x4[lane + 32 * j];
            float4 a = ua4[lane + 32 * j];
            float4 b = ub4[lane + 32 * j];
            sa += x.x * a.x + x.y * a.y + x.z * a.z + x.w * a.w;
            sb += x.x * b.x + x.y * b.y + x.z * b.z + x.w * b.w;
        }
        #pragma unroll
        for (int o = 16; o; o >>= 1) {
            sa += __shfl_xor_sync(0xffffffffu, sa, o);
            sb += __shfl_xor_sync(0xffffffffu, sb, o);
        }
        if (lane == 0) { pa[v] = sa; pb[v] = sb; }
    }
}

// ---------------------------------------------------------------------------
// Initialize all four output quarters with their constants.
// ---------------------------------------------------------------------------
__global__ void init_out(float* __restrict__ out, const float* __restrict__ kc, int n)
{
    int i = blockIdx.x * 256 + threadIdx.x;
    if (i < n) {
        float k1 = kc[0], k2 = kc[1];
        out[i]         = k1;   // sc1 = h2.v1
        out[n + i]     = k2;   // sc2 = h1.v2
        out[2 * n + i] = k1;   // sc3 = h4.v1
        out[3 * n + i] = k2;   // sc4 = h3.v2
    }
}

// ---------------------------------------------------------------------------
// Scatter-add: for each edge, oa[dst] += pa[src]; ob[dst] += pb[src]
// p arrays are 400 KB each -> L2 resident gathers. 4 edges per thread.
// ---------------------------------------------------------------------------
__global__ __launch_bounds__(256) void scatter2(
    const int* __restrict__ src, const int* __restrict__ dst,
    const float* __restrict__ pa, const float* __restrict__ pb,
    float* __restrict__ oa, float* __restrict__ ob, int ne)
{
    int base = blockIdx.x * 1024 + threadIdx.x;
    #pragma unroll
    for (int j = 0; j < 4; j++) {
        int e = base + j * 256;
        if (e < ne) {
            int s = src[e], d = dst[e];
            atomicAdd(&oa[d], __ldg(&pa[s]));
            atomicAdd(&ob[d], __ldg(&pb[s]));
        }
    }
}

// ---------------------------------------------------------------------------
// Launch
// ---------------------------------------------------------------------------
extern "C" void kernel_launch(void* const* d_in, const int* in_sizes, int n_in,
                              void* d_out, int out_size)
{
    const float* feat = (const float*)d_in[0];
    const float* shuf = (const float*)d_in[1];
    const int*   src1 = (const int*)d_in[2];
    const int*   dst1 = (const int*)d_in[3];
    const int*   src2 = (const int*)d_in[4];
    const int*   dst2 = (const int*)d_in[5];
    const float* W1   = (const float*)d_in[6];
    const float* b1   = (const float*)d_in[7];
    const float* W2   = (const float*)d_in[8];
    const float* b2   = (const float*)d_in[9];
    const float* Wb   = (const float*)d_in[10];
    const float* bb   = (const float*)d_in[11];
    float* out = (float*)d_out;

    const int n   = in_sizes[0] / IN_DIM;   // 100000
    const int ne1 = in_sizes[2];
    const int ne2 = in_sizes[4];

    void* p;
    cudaGetSymbolAddress(&p, g_deg); int*   deg = (int*)p;
    cudaGetSymbolAddress(&p, g_wf);  float* wf  = (float*)p;
    cudaGetSymbolAddress(&p, g_u);   float* u   = (float*)p;
    cudaGetSymbolAddress(&p, g_k);   float* kc  = (float*)p;
    cudaGetSymbolAddress(&p, g_p);   float* pp  = (float*)p;

    float* pfa = pp;            // feat @ u_a  -> out[0:n]   via edges2
    float* pfb = pp + NN;       // feat @ u_b  -> out[n:2n]  via edges1
    float* psa = pp + 2 * NN;   // shuf @ u_a  -> out[2n:3n] via edges2
    float* psb = pp + 3 * NN;   // shuf @ u_b  -> out[3n:4n] via edges1

    // 0) zero degree + wf accumulators
    cudaMemsetAsync(deg, 0, 2 * NN * sizeof(int));
    cudaMemsetAsync(wf, 0, 2 * IN_DIM * sizeof(float));

    // 1) out-degree histograms over src lists
    hist4<<<(ne1 + 1023) / 1024, 256>>>(src1, deg, ne1);
    hist4<<<(ne2 + 1023) / 1024, 256>>>(src2, deg + NN, ne2);

    // 2) weighted row-sums of feat (one streaming pass, both weightings)
    wf_kernel<<<2048, 256>>>(feat, deg, deg + NN, wf, n);

    // 3) tiny serial chain -> u vectors + constants
    tiny_kernel<<<1, 512>>>(W1, b1, W2, b2, Wb, bb, wf, u, kc, 1.0f / (float)n);

    // 4) per-node projections (two streaming passes)
    p_kernel<<<(n + 7) / 8, 256>>>(feat, u, pfa, pfb, n);
    p_kernel<<<(n + 7) / 8, 256>>>(shuf, u, psa, psb, n);

    // 5) initialize output with constants
    init_out<<<(n + 255) / 256, 256>>>(out, kc, n);

    // 6) edge scatter-adds
    scatter2<<<(ne2 + 1023) / 1024, 256>>>(src2, dst2, pfa, psa, out, out + 2 * n, ne2);
    scatter2<<<(ne1 + 1023) / 1024, 256>>>(src1, dst1, pfb, psb, out + n, out + 3 * n, ne1);
}

// round 4
// speedup vs baseline: 5.0250x; 1.4868x over previous
#include <cuda_runtime.h>
#include <cstdint>
#include <math.h>

#define NN      100000
#define IN_DIM  512
#define OUT_DIM 128

// ---------------------------------------------------------------------------
// Scratch (__device__ globals; no cudaMalloc allowed).
// ---------------------------------------------------------------------------
__device__ int   g_deg [2 * NN];         // outdeg over src1, src2
__device__ float g_wf  [2 * IN_DIM];     // weighted row-sums of feat
__device__ float g_cpre[2 * OUT_DIM];    // pre-sigmoid c sums (before /n, +b)
__device__ float g_v   [2 * OUT_DIM];    // v1 = Wb@c1, v2 = Wb@c2
__device__ float g_u   [2 * IN_DIM];     // u_a = W2@v1, u_b = W1@v2
__device__ float g_k   [2];              // k1 = b2.v1+bb, k2 = b1.v2+bb
__device__ float g_p   [4 * NN];         // pfa, pfb, psa, psb

// ---------------------------------------------------------------------------
// Histogram: outdeg[src[e]]++  — int4 loads, 4 edges/thread
// ---------------------------------------------------------------------------
__global__ void hist4(const int* __restrict__ src, int* __restrict__ deg, int ne)
{
    int i = blockIdx.x * blockDim.x + threadIdx.x;
    int e0 = i * 4;
    if (e0 + 3 < ne) {
        int4 s = *(const int4*)(src + e0);
        atomicAdd(&deg[s.x], 1);
        atomicAdd(&deg[s.y], 1);
        atomicAdd(&deg[s.z], 1);
        atomicAdd(&deg[s.w], 1);
    } else {
        for (int e = e0; e < ne; e++) atomicAdd(&deg[src[e]], 1);
    }
}

// ---------------------------------------------------------------------------
// wf[c]      = sum_v outdeg1[v] * feat[v,c]
// wf[512+c]  = sum_v outdeg2[v] * feat[v,c]
// ---------------------------------------------------------------------------
__global__ __launch_bounds__(256) void wf_kernel(
    const float* __restrict__ feat, const int* __restrict__ deg1,
    const int* __restrict__ deg2, float* __restrict__ wf, int n)
{
    int t = threadIdx.x;
    float a0 = 0.f, a1 = 0.f, b0 = 0.f, b1 = 0.f;
    for (int v = blockIdx.x; v < n; v += gridDim.x) {
        float w1 = (float)__ldg(&deg1[v]);
        float w2 = (float)__ldg(&deg2[v]);
        const float* row = feat + (size_t)v * IN_DIM;
        float x0 = __ldg(&row[t]);
        float x1 = __ldg(&row[t + 256]);
        a0 += w1 * x0; a1 += w1 * x1;
        b0 += w2 * x0; b1 += w2 * x1;
    }
    atomicAdd(&wf[t],                a0);
    atomicAdd(&wf[t + 256],          a1);
    atomicAdd(&wf[IN_DIM + t],       b0);
    atomicAdd(&wf[IN_DIM + t + 256], b1);
}

// ---------------------------------------------------------------------------
// cpre[h*128+t] = sum_k wf[h*512+k] * Wh[k,t]   — 16 blocks (2 halves x 8
// k-chunks of 64), coalesced W reads, atomic partial sums.
// ---------------------------------------------------------------------------
__global__ __launch_bounds__(128) void cpre_kernel(
    const float* __restrict__ W1, const float* __restrict__ W2,
    const float* __restrict__ wf, float* __restrict__ cpre)
{
    int hh = blockIdx.x >> 3;
    int chunk = blockIdx.x & 7;
    const float* W = hh ? W2 : W1;
    const float* w = wf + hh * IN_DIM + chunk * 64;
    const float* Wc = W + (size_t)(chunk * 64) * OUT_DIM + threadIdx.x;
    float s = 0.f;
    #pragma unroll 16
    for (int k = 0; k < 64; k++)
        s += __ldg(&w[k]) * __ldg(&Wc[k * OUT_DIM]);
    atomicAdd(&cpre[hh * OUT_DIM + threadIdx.x], s);
}

// ---------------------------------------------------------------------------
// v[h*128+d] = sum_e Wb[d,e] * sigmoid(cpre[h*128+e]/n + b[e])
// Warp per output (256 warps). Sigmoids recomputed per-lane (4 each, MUFU).
// ---------------------------------------------------------------------------
__global__ __launch_bounds__(128) void v_kernel(
    const float* __restrict__ Wb, const float* __restrict__ cpre,
    const float* __restrict__ b1, const float* __restrict__ b2,
    float* __restrict__ v, float inv_n)
{
    int gw = blockIdx.x * 4 + (threadIdx.x >> 5);   // 0..255
    int lane = threadIdx.x & 31;
    int half = gw >> 7;
    int d = gw & 127;
    const float* bh = half ? b2 : b1;
    const float* cp = cpre + half * OUT_DIM;
    const float* wr = Wb + (size_t)d * OUT_DIM;
    float s = 0.f;
    #pragma unroll
    for (int j = 0; j < 4; j++) {
        int e = lane + 32 * j;
        float c = 1.0f / (1.0f + expf(-(__ldg(&cp[e]) * inv_n + __ldg(&bh[e]))));
        s += __ldg(&wr[e]) * c;
    }
    #pragma unroll
    for (int o = 16; o; o >>= 1) s += __shfl_xor_sync(0xffffffffu, s, o);
    if (lane == 0) v[half * OUT_DIM + d] = s;
}

// ---------------------------------------------------------------------------
// u_a[t] = sum_d W2[t,d] v1[d] ; u_b[t] = sum_d W1[t,d] v2[d]
// Warp per output (1024 warps, 256 blocks). Block 256: k constants.
// ---------------------------------------------------------------------------
__global__ __launch_bounds__(128) void u_kernel(
    const float* __restrict__ W1, const float* __restrict__ W2,
    const float* __restrict__ b1, const float* __restrict__ b2,
    const float* __restrict__ bb, const float* __restrict__ v,
    float* __restrict__ u, float* __restrict__ kc)
{
    int warp = threadIdx.x >> 5, lane = threadIdx.x & 31;
    if (blockIdx.x == 256) {                 // k constants: 2 warps
        if (warp >= 2) return;
        const float* bv = warp ? b1 : b2;    // k1 = b2.v1, k2 = b1.v2
        const float* vv = v + warp * OUT_DIM;
        float s = 0.f;
        #pragma unroll
        for (int j = 0; j < 4; j++) {
            int d = lane + 32 * j;
            s += __ldg(&bv[d]) * __ldg(&vv[d]);
        }
        #pragma unroll
        for (int o = 16; o; o >>= 1) s += __shfl_xor_sync(0xffffffffu, s, o);
        if (lane == 0) kc[warp] = s + __ldg(bb);
        return;
    }
    int gw = blockIdx.x * 4 + warp;          // 0..1023
    int half = gw >> 9;                      // 0: u_a (W2,v1)  1: u_b (W1,v2)
    int t = gw & 511;
    const float* W = half ? W1 : W2;
    const float* vv = v + half * OUT_DIM;
    const float* wr = W + (size_t)t * OUT_DIM;
    float s = 0.f;
    #pragma unroll
    for (int j = 0; j < 4; j++) {
        int d = lane + 32 * j;
        s += __ldg(&wr[d]) * __ldg(&vv[d]);
    }
    #pragma unroll
    for (int o = 16; o; o >>= 1) s += __shfl_xor_sync(0xffffffffu, s, o);
    if (lane == 0) u[half * IN_DIM + t] = s;
}

// ---------------------------------------------------------------------------
// p GEMVs over both feat and shuf in one launch (warp per node).
// ---------------------------------------------------------------------------
__global__ __launch_bounds__(256) void p_kernel(
    const float* __restrict__ feat, const float* __restrict__ shuf,
    const float* __restrict__ u, float* __restrict__ pp, int n)
{
    __shared__ __align__(16) float su[2 * IN_DIM];
    for (int i = threadIdx.x; i < 2 * IN_DIM; i += 256) su[i] = u[i];
    __syncthreads();

    int warp = threadIdx.x >> 5, lane = threadIdx.x & 31;
    int idx = blockIdx.x * 8 + warp;          // 0 .. 2n-1
    if (idx >= 2 * n) return;
    const float* X;
    float* pa;
    float* pb;
    int v;
    if (idx < n) { X = feat; v = idx;     pa = pp;          pb = pp + NN; }
    else         { X = shuf; v = idx - n; pa = pp + 2 * NN; pb = pp + 3 * NN; }

    const float4* x4 = (const float4*)(X + (size_t)v * IN_DIM);
    const float4* ua4 = (const float4*)su;
    const float4* ub4 = (const float4*)(su + IN_DIM);
    float sa = 0.f, sb = 0.f;
    #pragma unroll
    for (int j = 0; j < 4; j++) {
        float4 x = x4[lane + 32 * j];
        float4 a = ua4[lane + 32 * j];
        float4 b = ub4[lane + 32 * j];
        sa += x.x * a.x + x.y * a.y + x.z * a.z + x.w * a.w;
        sb += x.x * b.x + x.y * b.y + x.z * b.z + x.w * b.w;
    }
    #pragma unroll
    for (int o = 16; o; o >>= 1) {
        sa += __shfl_xor_sync(0xffffffffu, sa, o);
        sb += __shfl_xor_sync(0xffffffffu, sb, o);
    }
    if (lane == 0) { pa[v] = sa; pb[v] = sb; }
}

// ---------------------------------------------------------------------------
// Initialize all four output quarters with their constants.
// ---------------------------------------------------------------------------
__global__ void init_out(float* __restrict__ out, const float* __restrict__ kc, int n)
{
    int i = blockIdx.x * 256 + threadIdx.x;
    if (i < n) {
        float k1 = kc[0], k2 = kc[1];
        out[i]         = k1;   // sc1 = h2.v1
        out[n + i]     = k2;   // sc2 = h1.v2
        out[2 * n + i] = k1;   // sc3 = h4.v1
        out[3 * n + i] = k2;   // sc4 = h3.v2
    }
}

// ---------------------------------------------------------------------------
// Scatter-add: oa[dst] += pa[src]; ob[dst] += pb[src]  — int4 edge loads.
// ---------------------------------------------------------------------------
__global__ __launch_bounds__(256) void scatter2(
    const int* __restrict__ src, const int* __restrict__ dst,
    const float* __restrict__ pa, const float* __restrict__ pb,
    float* __restrict__ oa, float* __restrict__ ob, int ne)
{
    int i = blockIdx.x * blockDim.x + threadIdx.x;
    int e0 = i * 4;
    if (e0 + 3 < ne) {
        int4 s = *(const int4*)(src + e0);
        int4 d = *(const int4*)(dst + e0);
        atomicAdd(&oa[d.x], __ldg(&pa[s.x]));
        atomicAdd(&ob[d.x], __ldg(&pb[s.x]));
        atomicAdd(&oa[d.y], __ldg(&pa[s.y]));
        atomicAdd(&ob[d.y], __ldg(&pb[s.y]));
        atomicAdd(&oa[d.z], __ldg(&pa[s.z]));
        atomicAdd(&ob[d.z], __ldg(&pb[s.z]));
        atomicAdd(&oa[d.w], __ldg(&pa[s.w]));
        atomicAdd(&ob[d.w], __ldg(&pb[s.w]));
    } else {
        for (int e = e0; e < ne; e++) {
            int s = src[e], d = dst[e];
            atomicAdd(&oa[d], __ldg(&pa[s]));
            atomicAdd(&ob[d], __ldg(&pb[s]));
        }
    }
}

// ---------------------------------------------------------------------------
// Launch
// ---------------------------------------------------------------------------
extern "C" void kernel_launch(void* const* d_in, const int* in_sizes, int n_in,
                              void* d_out, int out_size)
{
    const float* feat = (const float*)d_in[0];
    const float* shuf = (const float*)d_in[1];
    const int*   src1 = (const int*)d_in[2];
    const int*   dst1 = (const int*)d_in[3];
    const int*   src2 = (const int*)d_in[4];
    const int*   dst2 = (const int*)d_in[5];
    const float* W1   = (const float*)d_in[6];
    const float* b1   = (const float*)d_in[7];
    const float* W2   = (const float*)d_in[8];
    const float* b2   = (const float*)d_in[9];
    const float* Wb   = (const float*)d_in[10];
    const float* bb   = (const float*)d_in[11];
    float* out = (float*)d_out;

    const int n   = in_sizes[0] / IN_DIM;   // 100000
    const int ne1 = in_sizes[2];
    const int ne2 = in_sizes[4];

    void* p;
    cudaGetSymbolAddress(&p, g_deg);  int*   deg  = (int*)p;
    cudaGetSymbolAddress(&p, g_wf);   float* wf   = (float*)p;
    cudaGetSymbolAddress(&p, g_cpre); float* cpre = (float*)p;
    cudaGetSymbolAddress(&p, g_v);    float* v    = (float*)p;
    cudaGetSymbolAddress(&p, g_u);    float* u    = (float*)p;
    cudaGetSymbolAddress(&p, g_k);    float* kc   = (float*)p;
    cudaGetSymbolAddress(&p, g_p);    float* pp   = (float*)p;

    // 0) zero accumulators
    cudaMemsetAsync(deg, 0, 2 * NN * sizeof(int));
    cudaMemsetAsync(wf, 0, 2 * IN_DIM * sizeof(float));
    cudaMemsetAsync(cpre, 0, 2 * OUT_DIM * sizeof(float));

    // 1) out-degree histograms over src lists
    hist4<<<(ne1 / 4 + 255) / 256, 256>>>(src1, deg, ne1);
    hist4<<<(ne2 / 4 + 255) / 256, 256>>>(src2, deg + NN, ne2);

    // 2) weighted row-sums of feat
    wf_kernel<<<2048, 256>>>(feat, deg, deg + NN, wf, n);

    // 3) parallel tiny chain: cpre -> v -> u (+k)
    cpre_kernel<<<16, 128>>>(W1, W2, wf, cpre);
    v_kernel<<<64, 128>>>(Wb, cpre, b1, b2, v, 1.0f / (float)n);
    u_kernel<<<257, 128>>>(W1, W2, b1, b2, bb, v, u, kc);

    // 4) init output with constants (needs kc only)
    init_out<<<(n + 255) / 256, 256>>>(out, kc, n);

    // 5) per-node projections (feat + shuf in one launch)
    p_kernel<<<(2 * n + 7) / 8, 256>>>(feat, shuf, u, pp, n);

    // 6) edge scatter-adds
    scatter2<<<(ne2 / 4 + 255) / 256, 256>>>(src2, dst2, pp, pp + 2 * NN,
                                             out, out + 2 * n, ne2);
    scatter2<<<(ne1 / 4 + 255) / 256, 256>>>(src1, dst1, pp + NN, pp + 3 * NN,
                                             out + n, out + 3 * n, ne1);
}

// round 5
// speedup vs baseline: 5.4644x; 1.0874x over previous
#include <cuda_runtime.h>
#include <cstdint>
#include <math.h>

#define NN      100000
#define IN_DIM  512
#define OUT_DIM 128

// ---------------------------------------------------------------------------
// Scratch: one packed block so a single memset zeroes deg+wf+cpre.
// Layout: [0, 2*NN) int deg | [2*NN, +1024) float wf | [+1024, +256) float cpre
// ---------------------------------------------------------------------------
#define ZERO_INTS (2 * NN + 1024 + 256)
__device__ int   g_zero[ZERO_INTS];      // deg, wf, cpre (all zero-init per call)
__device__ float g_v   [2 * OUT_DIM];    // v1 = Wb@c1, v2 = Wb@c2
__device__ float g_u   [2 * IN_DIM];     // u_a = W2@v1, u_b = W1@v2
__device__ float g_k   [2];              // k1 = b2.v1+bb, k2 = b1.v2+bb
__device__ float g_p   [4 * NN];         // pfa, pfb, psa, psb

// ---------------------------------------------------------------------------
// Histogram over both src lists in one launch (blockIdx.y selects list).
// ---------------------------------------------------------------------------
__global__ void hist_both(const int* __restrict__ srcA, int neA,
                          const int* __restrict__ srcB, int neB,
                          int* __restrict__ deg)
{
    const int* src = blockIdx.y ? srcB : srcA;
    int ne = blockIdx.y ? neB : neA;
    int* dg = deg + blockIdx.y * NN;
    int e0 = (blockIdx.x * blockDim.x + threadIdx.x) * 4;
    if (e0 + 3 < ne) {
        int4 s = *(const int4*)(src + e0);
        atomicAdd(&dg[s.x], 1);
        atomicAdd(&dg[s.y], 1);
        atomicAdd(&dg[s.z], 1);
        atomicAdd(&dg[s.w], 1);
    } else {
        for (int e = e0; e < ne; e++) atomicAdd(&dg[src[e]], 1);
    }
}

// ---------------------------------------------------------------------------
// wf[c]     = sum_v deg1[v] * feat[v,c]
// wf[512+c] = sum_v deg2[v] * feat[v,c]
// 256 threads: two row-halves x 128 float4 column groups. Block-level smem
// reduction, then 8 atomics per surviving thread (1024 atomics/block).
// ---------------------------------------------------------------------------
__global__ __launch_bounds__(256) void wf_kernel(
    const float* __restrict__ feat, const int* __restrict__ deg1,
    const int* __restrict__ deg2, float* __restrict__ wf, int n)
{
    __shared__ float red[256 * 8];
    int t = threadIdx.x;
    int half = t >> 7, c = t & 127;
    const float4* f4 = (const float4*)feat;

    float4 a1 = make_float4(0.f, 0.f, 0.f, 0.f);
    float4 a2 = make_float4(0.f, 0.f, 0.f, 0.f);
    for (int v = blockIdx.x * 2 + half; v < n; v += gridDim.x * 2) {
        float w1 = (float)__ldg(&deg1[v]);
        float w2 = (float)__ldg(&deg2[v]);
        float4 x = __ldg(&f4[(size_t)v * 128 + c]);
        a1.x += w1 * x.x; a1.y += w1 * x.y; a1.z += w1 * x.z; a1.w += w1 * x.w;
        a2.x += w2 * x.x; a2.y += w2 * x.y; a2.z += w2 * x.z; a2.w += w2 * x.w;
    }
    *(float4*)&red[t * 8]     = a1;
    *(float4*)&red[t * 8 + 4] = a2;
    __syncthreads();
    if (half == 0) {
        int p = (t + 128) * 8;
        a1.x += red[p];     a1.y += red[p + 1]; a1.z += red[p + 2]; a1.w += red[p + 3];
        a2.x += red[p + 4]; a2.y += red[p + 5]; a2.z += red[p + 6]; a2.w += red[p + 7];
        atomicAdd(&wf[c * 4],     a1.x);
        atomicAdd(&wf[c * 4 + 1], a1.y);
        atomicAdd(&wf[c * 4 + 2], a1.z);
        atomicAdd(&wf[c * 4 + 3], a1.w);
        atomicAdd(&wf[IN_DIM + c * 4],     a2.x);
        atomicAdd(&wf[IN_DIM + c * 4 + 1], a2.y);
        atomicAdd(&wf[IN_DIM + c * 4 + 2], a2.z);
        atomicAdd(&wf[IN_DIM + c * 4 + 3], a2.w);
    }
}

// ---------------------------------------------------------------------------
// cpre[h*128+t] = sum_k wf[h*512+k] * Wh[k,t] — 128 blocks (2 halves x 64
// k-chunks of 8), coalesced W reads, atomic partial sums.
// ---------------------------------------------------------------------------
__global__ __launch_bounds__(128) void cpre_kernel(
    const float* __restrict__ W1, const float* __restrict__ W2,
    const float* __restrict__ wf, float* __restrict__ cpre)
{
    int hh = blockIdx.x >> 6;
    int chunk = blockIdx.x & 63;
    const float* W = hh ? W2 : W1;
    const float* w = wf + hh * IN_DIM + chunk * 8;
    const float* Wc = W + (size_t)(chunk * 8) * OUT_DIM + threadIdx.x;
    float s = 0.f;
    #pragma unroll
    for (int k = 0; k < 8; k++)
        s += __ldg(&w[k]) * __ldg(&Wc[k * OUT_DIM]);
    atomicAdd(&cpre[hh * OUT_DIM + threadIdx.x], s);
}

// ---------------------------------------------------------------------------
// v[h*128+d] = sum_e Wb[d,e] * sigmoid(cpre[h*128+e]/n + b[e])
// Warp per output (256 warps).
// ---------------------------------------------------------------------------
__global__ __launch_bounds__(128) void v_kernel(
    const float* __restrict__ Wb, const float* __restrict__ cpre,
    const float* __restrict__ b1, const float* __restrict__ b2,
    float* __restrict__ v, float inv_n)
{
    int gw = blockIdx.x * 4 + (threadIdx.x >> 5);   // 0..255
    int lane = threadIdx.x & 31;
    int half = gw >> 7;
    int d = gw & 127;
    const float* bh = half ? b2 : b1;
    const float* cp = cpre + half * OUT_DIM;
    const float* wr = Wb + (size_t)d * OUT_DIM;
    float s = 0.f;
    #pragma unroll
    for (int j = 0; j < 4; j++) {
        int e = lane + 32 * j;
        float c = 1.0f / (1.0f + expf(-(__ldg(&cp[e]) * inv_n + __ldg(&bh[e]))));
        s += __ldg(&wr[e]) * c;
    }
    #pragma unroll
    for (int o = 16; o; o >>= 1) s += __shfl_xor_sync(0xffffffffu, s, o);
    if (lane == 0) v[half * OUT_DIM + d] = s;
}

// ---------------------------------------------------------------------------
// u_a[t] = sum_d W2[t,d] v1[d] ; u_b[t] = sum_d W1[t,d] v2[d]
// Warp per output (1024 warps). Block 256: k constants.
// ---------------------------------------------------------------------------
__global__ __launch_bounds__(128) void u_kernel(
    const float* __restrict__ W1, const float* __restrict__ W2,
    const float* __restrict__ b1, const float* __restrict__ b2,
    const float* __restrict__ bb, const float* __restrict__ v,
    float* __restrict__ u, float* __restrict__ kc)
{
    int warp = threadIdx.x >> 5, lane = threadIdx.x & 31;
    if (blockIdx.x == 256) {                 // k constants: 2 warps
        if (warp >= 2) return;
        const float* bv = warp ? b1 : b2;    // k1 = b2.v1, k2 = b1.v2
        const float* vv = v + warp * OUT_DIM;
        float s = 0.f;
        #pragma unroll
        for (int j = 0; j < 4; j++) {
            int d = lane + 32 * j;
            s += __ldg(&bv[d]) * __ldg(&vv[d]);
        }
        #pragma unroll
        for (int o = 16; o; o >>= 1) s += __shfl_xor_sync(0xffffffffu, s, o);
        if (lane == 0) kc[warp] = s + __ldg(bb);
        return;
    }
    int gw = blockIdx.x * 4 + warp;          // 0..1023
    int half = gw >> 9;                      // 0: u_a (W2,v1)  1: u_b (W1,v2)
    int t = gw & 511;
    const float* W = half ? W1 : W2;
    const float* vv = v + half * OUT_DIM;
    const float* wr = W + (size_t)t * OUT_DIM;
    float s = 0.f;
    #pragma unroll
    for (int j = 0; j < 4; j++) {
        int d = lane + 32 * j;
        s += __ldg(&wr[d]) * __ldg(&vv[d]);
    }
    #pragma unroll
    for (int o = 16; o; o >>= 1) s += __shfl_xor_sync(0xffffffffu, s, o);
    if (lane == 0) u[half * IN_DIM + t] = s;
}

// ---------------------------------------------------------------------------
// Initialize all four output quarters with their constants.
// ---------------------------------------------------------------------------
__global__ void init_out(float* __restrict__ out, const float* __restrict__ kc, int n)
{
    int i = blockIdx.x * 256 + threadIdx.x;
    if (i < n) {
        float k1 = kc[0], k2 = kc[1];
        out[i]         = k1;   // sc1 = h2.v1
        out[n + i]     = k2;   // sc2 = h1.v2
        out[2 * n + i] = k1;   // sc3 = h4.v1
        out[3 * n + i] = k2;   // sc4 = h3.v2
    }
}

// ---------------------------------------------------------------------------
// p GEMVs over both feat and shuf in one launch (warp per node).
// ---------------------------------------------------------------------------
__global__ __launch_bounds__(512) void p_kernel(
    const float* __restrict__ feat, const float* __restrict__ shuf,
    const float* __restrict__ u, float* __restrict__ pp, int n)
{
    __shared__ __align__(16) float su[2 * IN_DIM];
    for (int i = threadIdx.x; i < 2 * IN_DIM; i += 512) su[i] = u[i];
    __syncthreads();

    int warp = threadIdx.x >> 5, lane = threadIdx.x & 31;
    int idx = blockIdx.x * 16 + warp;          // 0 .. 2n-1
    if (idx >= 2 * n) return;
    const float* X;
    float* pa;
    float* pb;
    int v;
    if (idx < n) { X = feat; v = idx;     pa = pp;          pb = pp + NN; }
    else         { X = shuf; v = idx - n; pa = pp + 2 * NN; pb = pp + 3 * NN; }

    const float4* x4 = (const float4*)(X + (size_t)v * IN_DIM);
    const float4* ua4 = (const float4*)su;
    const float4* ub4 = (const float4*)(su + IN_DIM);
    float sa = 0.f, sb = 0.f;
    #pragma unroll
    for (int j = 0; j < 4; j++) {
        float4 x = x4[lane + 32 * j];
        float4 a = ua4[lane + 32 * j];
        float4 b = ub4[lane + 32 * j];
        sa += x.x * a.x + x.y * a.y + x.z * a.z + x.w * a.w;
        sb += x.x * b.x + x.y * b.y + x.z * b.z + x.w * b.w;
    }
    #pragma unroll
    for (int o = 16; o; o >>= 1) {
        sa += __shfl_xor_sync(0xffffffffu, sa, o);
        sb += __shfl_xor_sync(0xffffffffu, sb, o);
    }
    if (lane == 0) { pa[v] = sa; pb[v] = sb; }
}

// ---------------------------------------------------------------------------
// Scatter-add for both edge lists in one launch (blockIdx.y selects list).
//   y=0: edges2 -> oa=out[0:n] (pfa), ob=out[2n:3n] (psa)
//   y=1: edges1 -> oa=out[n:2n] (pfb), ob=out[3n:4n] (psb)
// ---------------------------------------------------------------------------
__global__ __launch_bounds__(256) void scatter_both(
    const int* __restrict__ src2, const int* __restrict__ dst2, int ne2,
    const int* __restrict__ src1, const int* __restrict__ dst1, int ne1,
    const float* __restrict__ pp, float* __restrict__ out, int n)
{
    const int* src; const int* dst; const float* pa; const float* pb;
    float* oa; float* ob; int ne;
    if (blockIdx.y == 0) {
        src = src2; dst = dst2; ne = ne2;
        pa = pp;          pb = pp + 2 * NN;
        oa = out;         ob = out + 2 * n;
    } else {
        src = src1; dst = dst1; ne = ne1;
        pa = pp + NN;     pb = pp + 3 * NN;
        oa = out + n;     ob = out + 3 * n;
    }
    int e0 = (blockIdx.x * blockDim.x + threadIdx.x) * 4;
    if (e0 + 3 < ne) {
        int4 s = *(const int4*)(src + e0);
        int4 d = *(const int4*)(dst + e0);
        atomicAdd(&oa[d.x], __ldg(&pa[s.x]));
        atomicAdd(&ob[d.x], __ldg(&pb[s.x]));
        atomicAdd(&oa[d.y], __ldg(&pa[s.y]));
        atomicAdd(&ob[d.y], __ldg(&pb[s.y]));
        atomicAdd(&oa[d.z], __ldg(&pa[s.z]));
        atomicAdd(&ob[d.z], __ldg(&pb[s.z]));
        atomicAdd(&oa[d.w], __ldg(&pa[s.w]));
        atomicAdd(&ob[d.w], __ldg(&pb[s.w]));
    } else {
        for (int e = e0; e < ne; e++) {
            int s = src[e], d = dst[e];
            atomicAdd(&oa[d], __ldg(&pa[s]));
            atomicAdd(&ob[d], __ldg(&pb[s]));
        }
    }
}

// ---------------------------------------------------------------------------
// Launch
// ---------------------------------------------------------------------------
extern "C" void kernel_launch(void* const* d_in, const int* in_sizes, int n_in,
                              void* d_out, int out_size)
{
    const float* feat = (const float*)d_in[0];
    const float* shuf = (const float*)d_in[1];
    const int*   src1 = (const int*)d_in[2];
    const int*   dst1 = (const int*)d_in[3];
    const int*   src2 = (const int*)d_in[4];
    const int*   dst2 = (const int*)d_in[5];
    const float* W1   = (const float*)d_in[6];
    const float* b1   = (const float*)d_in[7];
    const float* W2   = (const float*)d_in[8];
    const float* b2   = (const float*)d_in[9];
    const float* Wb   = (const float*)d_in[10];
    const float* bb   = (const float*)d_in[11];
    float* out = (float*)d_out;

    const int n   = in_sizes[0] / IN_DIM;   // 100000
    const int ne1 = in_sizes[2];
    const int ne2 = in_sizes[4];

    void* p;
    cudaGetSymbolAddress(&p, g_zero);
    int*   deg  = (int*)p;
    float* wf   = (float*)p + 2 * NN;
    float* cpre = (float*)p + 2 * NN + 1024;
    cudaGetSymbolAddress(&p, g_v);    float* v    = (float*)p;
    cudaGetSymbolAddress(&p, g_u);    float* u    = (float*)p;
    cudaGetSymbolAddress(&p, g_k);    float* kc   = (float*)p;
    cudaGetSymbolAddress(&p, g_p);    float* pp   = (float*)p;

    // 0) zero deg+wf+cpre with one memset
    cudaMemsetAsync(deg, 0, ZERO_INTS * sizeof(int));

    // 1) out-degree histograms (both lists, one launch)
    {
        int gx1 = (ne1 / 4 + 255) / 256, gx2 = (ne2 / 4 + 255) / 256;
        dim3 grid(gx1 > gx2 ? gx1 : gx2, 2);
        hist_both<<<grid, 256>>>(src1, ne1, src2, ne2, deg);
    }

    // 2) weighted row-sums of feat
    wf_kernel<<<1024, 256>>>(feat, deg, deg + NN, wf, n);

    // 3) parallel tiny chain: cpre -> v -> u (+k)
    cpre_kernel<<<128, 128>>>(W1, W2, wf, cpre);
    v_kernel<<<64, 128>>>(Wb, cpre, b1, b2, v, 1.0f / (float)n);
    u_kernel<<<257, 128>>>(W1, W2, b1, b2, bb, v, u, kc);

    // 4) init output with constants (off the critical tail: before p)
    init_out<<<(n + 255) / 256, 256>>>(out, kc, n);

    // 5) per-node projections (feat + shuf in one launch)
    p_kernel<<<(2 * n + 15) / 16, 512>>>(feat, shuf, u, pp, n);

    // 6) edge scatter-adds (both lists, one launch)
    {
        int gx1 = (ne1 / 4 + 255) / 256, gx2 = (ne2 / 4 + 255) / 256;
        dim3 grid(gx1 > gx2 ? gx1 : gx2, 2);
        scatter_both<<<grid, 256>>>(src2, dst2, ne2, src1, dst1, ne1, pp, out, n);
    }
}